// round 3
// baseline (speedup 1.0000x reference)
#include <cuda_runtime.h>
#include <cuda_bf16.h>

// AffineAugment: per-batch rigid affine warp [B,H,W,D,1] fp32, trilinear, zero fill.
// B=4, H=W=D=192. Strategy: tile outputs per block, stage the (near-identity)
// input bounding box in SMEM via coalesced loads, gather 8 taps with LDS.
// Per-block fallback to direct global gather if bbox doesn't fit SMEM.

#define HH 192
#define WW 192
#define DD 192

#define TI 12                 // output tile extent along i (x)
#define TJ 16                 // along j (y)
#define TK 16                 // along k (z)
#define NTI (HH / TI)         // 16
#define NTJ (WW / TJ)         // 12
#define NTK (DD / TK)         // 12

#define SMEM_FLOATS 11008     // 43 KB -> 5 blocks/SM

__global__ void __launch_bounds__(256, 5)
affine_warp_tile(const float* __restrict__ x,
                 const float* __restrict__ mats,
                 float* __restrict__ out)
{
    __shared__ float s[SMEM_FLOATS];

    int blk = blockIdx.x;
    int tk = blk % NTK; blk /= NTK;
    int tj = blk % NTJ; blk /= NTJ;
    int ti = blk % NTI;
    int b  = blk / NTI;

    const int i0 = ti * TI, j0 = tj * TJ, k0 = tk * TK;

    const float* __restrict__ M = mats + b * 12;
    const float m00 = __ldg(M + 0), m01 = __ldg(M + 1), m02 = __ldg(M + 2), m03 = __ldg(M + 3);
    const float m10 = __ldg(M + 4), m11 = __ldg(M + 5), m12 = __ldg(M + 6), m13 = __ldg(M + 7);
    const float m20 = __ldg(M + 8), m21 = __ldg(M + 9), m22 = __ldg(M +10), m23 = __ldg(M +11);

    // ---- input bounding box of this output tile (corner extremes) ----
    float lox = m03, hix = m03, loy = m13, hiy = m13, loz = m23, hiz = m23;
    {
        float a, c;
        a = m00 * (float)i0; c = m00 * (float)(i0 + TI - 1); lox += fminf(a, c); hix += fmaxf(a, c);
        a = m01 * (float)j0; c = m01 * (float)(j0 + TJ - 1); lox += fminf(a, c); hix += fmaxf(a, c);
        a = m02 * (float)k0; c = m02 * (float)(k0 + TK - 1); lox += fminf(a, c); hix += fmaxf(a, c);

        a = m10 * (float)i0; c = m10 * (float)(i0 + TI - 1); loy += fminf(a, c); hiy += fmaxf(a, c);
        a = m11 * (float)j0; c = m11 * (float)(j0 + TJ - 1); loy += fminf(a, c); hiy += fmaxf(a, c);
        a = m12 * (float)k0; c = m12 * (float)(k0 + TK - 1); loy += fminf(a, c); hiy += fmaxf(a, c);

        a = m20 * (float)i0; c = m20 * (float)(i0 + TI - 1); loz += fminf(a, c); hiz += fmaxf(a, c);
        a = m21 * (float)j0; c = m21 * (float)(j0 + TJ - 1); loz += fminf(a, c); hiz += fmaxf(a, c);
        a = m22 * (float)k0; c = m22 * (float)(k0 + TK - 1); loz += fminf(a, c); hiz += fmaxf(a, c);
    }

    const int ixlo = max(0, (int)floorf(lox));
    const int ixhi = min(HH - 1, (int)floorf(hix) + 1);
    const int iylo = max(0, (int)floorf(loy));
    const int iyhi = min(WW - 1, (int)floorf(hiy) + 1);
    const int izlo = max(0, (int)floorf(loz));
    const int izhi = min(DD - 1, (int)floorf(hiz) + 1);

    const int kq = threadIdx.x & 15;       // k offset within tile
    const int jq = threadIdx.x >> 4;       // j offset within tile
    const int j  = j0 + jq;
    const int k  = k0 + kq;
    float* __restrict__ op = out + ((size_t)((b * HH + i0) * WW + j)) * DD + k;
    const size_t ostep = (size_t)WW * DD;

    const bool empty = (ixhi < ixlo) | (iyhi < iylo) | (izhi < izlo);
    if (empty) {
        // every voxel in the tile is out of range on some axis -> fill 0
        #pragma unroll
        for (int ii = 0; ii < TI; ii++) __stcs(op + (size_t)ii * ostep, 0.0f);
        return;
    }

    const int dx = ixhi - ixlo + 1;
    const int dy = iyhi - iylo + 1;
    const int dz = izhi - izlo + 1;
    const int dzp = dz | 1;                // pad to odd -> rotate banks per row
    const int xstep = dy * dzp;

    // per-voxel location base for this thread's (j,k); i added in the loop
    const float fj = (float)j, fk = (float)k;
    const float cx = fmaf(m01, fj, fmaf(m02, fk, m03));
    const float cy = fmaf(m11, fj, fmaf(m12, fk, m13));
    const float cz = fmaf(m21, fj, fmaf(m22, fk, m23));

    const float* __restrict__ vb = x + (size_t)b * (HH * WW * DD);

    const bool fits = (dz <= 32) && (dx * xstep <= SMEM_FLOATS);

    if (fits) {
        // ---- stage bbox into SMEM: one warp per (xx,yy) row, lane = z ----
        const int wid  = threadIdx.x >> 5;
        const int lane = threadIdx.x & 31;
        const int nrows = dx * dy;
        int xx = 0, yy = wid;
        while (yy >= dy) { yy -= dy; xx++; }
        for (int r = wid; r < nrows; r += 8) {
            if (lane < dz) {
                s[(xx * dy + yy) * dzp + lane] =
                    vb[((size_t)(ixlo + xx) * WW + (iylo + yy)) * DD + izlo + lane];
            }
            yy += 8;
            while (yy >= dy) { yy -= dy; xx++; }
        }
        __syncthreads();

        // ---- gather from SMEM ----
        #pragma unroll 4
        for (int ii = 0; ii < TI; ii++) {
            const float fi = (float)(i0 + ii);
            const float lx = fmaf(m00, fi, cx);
            const float ly = fmaf(m10, fi, cy);
            const float lz = fmaf(m20, fi, cz);

            float v = 0.0f;
            const bool valid =
                (lx >= 0.0f) & (lx <= (float)(HH - 1)) &
                (ly >= 0.0f) & (ly <= (float)(WW - 1)) &
                (lz >= 0.0f) & (lz <= (float)(DD - 1));
            if (valid) {
                const int ix0 = (int)lx;        // lx >= 0 -> trunc == floor
                const int iy0 = (int)ly;
                const int iz0 = (int)lz;
                const float tx = lx - (float)ix0;
                const float ty = ly - (float)iy0;
                const float tz = lz - (float)iz0;

                const int ox = (ix0 < HH - 1) ? xstep : 0;   // clamped +1 step
                const int oy = (iy0 < WW - 1) ? dzp   : 0;
                const int oz = (iz0 < DD - 1) ? 1     : 0;
                const int base = ((ix0 - ixlo) * dy + (iy0 - iylo)) * dzp + (iz0 - izlo);

                const float c000 = s[base];
                const float c001 = s[base + oz];
                const float c010 = s[base + oy];
                const float c011 = s[base + oy + oz];
                const float c100 = s[base + ox];
                const float c101 = s[base + ox + oz];
                const float c110 = s[base + ox + oy];
                const float c111 = s[base + ox + oy + oz];

                const float c00 = fmaf(tz, c001 - c000, c000);
                const float c01 = fmaf(tz, c011 - c010, c010);
                const float c10 = fmaf(tz, c101 - c100, c100);
                const float c11 = fmaf(tz, c111 - c110, c110);
                const float c0  = fmaf(ty, c01 - c00, c00);
                const float c1  = fmaf(ty, c11 - c10, c10);
                v = fmaf(tx, c1 - c0, c0);
            }
            __stcs(op + (size_t)ii * ostep, v);
        }
    } else {
        // ---- fallback: direct global gather (block-uniform branch) ----
        #pragma unroll 4
        for (int ii = 0; ii < TI; ii++) {
            const float fi = (float)(i0 + ii);
            const float lx = fmaf(m00, fi, cx);
            const float ly = fmaf(m10, fi, cy);
            const float lz = fmaf(m20, fi, cz);

            float v = 0.0f;
            const bool valid =
                (lx >= 0.0f) & (lx <= (float)(HH - 1)) &
                (ly >= 0.0f) & (ly <= (float)(WW - 1)) &
                (lz >= 0.0f) & (lz <= (float)(DD - 1));
            if (valid) {
                const int ix0 = (int)lx;
                const int iy0 = (int)ly;
                const int iz0 = (int)lz;
                const float tx = lx - (float)ix0;
                const float ty = ly - (float)iy0;
                const float tz = lz - (float)iz0;

                const int ox = (ix0 < HH - 1) ? (WW * DD) : 0;
                const int oy = (iy0 < WW - 1) ? DD        : 0;
                const int oz = (iz0 < DD - 1) ? 1         : 0;
                const int base = (ix0 * WW + iy0) * DD + iz0;

                const float c000 = __ldg(vb + base);
                const float c001 = __ldg(vb + base + oz);
                const float c010 = __ldg(vb + base + oy);
                const float c011 = __ldg(vb + base + oy + oz);
                const float c100 = __ldg(vb + base + ox);
                const float c101 = __ldg(vb + base + ox + oz);
                const float c110 = __ldg(vb + base + ox + oy);
                const float c111 = __ldg(vb + base + ox + oy + oz);

                const float c00 = fmaf(tz, c001 - c000, c000);
                const float c01 = fmaf(tz, c011 - c010, c010);
                const float c10 = fmaf(tz, c101 - c100, c100);
                const float c11 = fmaf(tz, c111 - c110, c110);
                const float c0  = fmaf(ty, c01 - c00, c00);
                const float c1  = fmaf(ty, c11 - c10, c10);
                v = fmaf(tx, c1 - c0, c0);
            }
            __stcs(op + (size_t)ii * ostep, v);
        }
    }
}

extern "C" void kernel_launch(void* const* d_in, const int* in_sizes, int n_in,
                              void* d_out, int out_size)
{
    const float* x    = (const float*)d_in[0];
    const float* mats = (const float*)d_in[1];
    float* out        = (float*)d_out;

    const int blocks = 4 * NTI * NTJ * NTK;   // 9216
    affine_warp_tile<<<blocks, 256>>>(x, mats, out);
}

// round 5
// speedup vs baseline: 1.0638x; 1.0638x over previous
#include <cuda_runtime.h>
#include <cuda_bf16.h>

// AffineAugment: per-batch rigid affine warp [B,H,W,D,1] fp32, trilinear, zero fill.
// B=4, H=W=D=192. Direct-gather, branchless (mask-multiplied) taps so the
// compiler can batch all loads of the 4-z unroll (high MLP), with a
// warp-uniform early-out for fully-invalid (fill=0) warps.

#define BB  4
#define HH  192
#define WW  192
#define DD  192
#define ZPT 4
#define NG  (DD / ZPT)        // 48 groups per (i,j) row

__global__ void __launch_bounds__(256, 6)
affine_warp_kernel(const float* __restrict__ x,
                   const float* __restrict__ mats,
                   float* __restrict__ out)
{
    // grid is an exact multiple: 4*192*192*48 / 256 = 27648 blocks, no tail
    int gid = blockIdx.x * blockDim.x + threadIdx.x;

    int g  = gid % NG;
    int t  = gid / NG;
    int j  = t % WW;  t /= WW;
    int i  = t % HH;
    int b  = t / HH;
    int k0 = g * ZPT;

    const float* __restrict__ M = mats + b * 12;
    const float m00 = __ldg(M + 0), m01 = __ldg(M + 1), m02 = __ldg(M + 2), m03 = __ldg(M + 3);
    const float m10 = __ldg(M + 4), m11 = __ldg(M + 5), m12 = __ldg(M + 6), m13 = __ldg(M + 7);
    const float m20 = __ldg(M + 8), m21 = __ldg(M + 9), m22 = __ldg(M +10), m23 = __ldg(M +11);

    const float fi = (float)i, fj = (float)j;
    const float b0 = fmaf(m00, fi, fmaf(m01, fj, m03));
    const float b1 = fmaf(m10, fi, fmaf(m11, fj, m13));
    const float b2 = fmaf(m20, fi, fmaf(m21, fj, m23));

    const float* __restrict__ vb = x + (size_t)b * (HH * WW * DD);

    float4* o4 = (float4*)(out + ((size_t)((b * HH + i) * WW + j) * DD + k0));

    // ---- cheap validity pre-pass: warp-uniform early out for fill regions ----
    int anyv = 0;
#pragma unroll
    for (int z = 0; z < ZPT; z++) {
        const float fk = (float)(k0 + z);
        const float lx = fmaf(m02, fk, b0);
        const float ly = fmaf(m12, fk, b1);
        const float lz = fmaf(m22, fk, b2);
        anyv |= (int)(lx >= 0.0f) & (int)(lx <= (float)(HH - 1)) &
                (int)(ly >= 0.0f) & (int)(ly <= (float)(WW - 1)) &
                (int)(lz >= 0.0f) & (int)(lz <= (float)(DD - 1));
    }
    if (!__any_sync(0xffffffffu, anyv)) {
        __stcs(o4, make_float4(0.0f, 0.0f, 0.0f, 0.0f));
        return;
    }

    // ---- branchless gather: clamped taps always loaded, result masked ----
    float res[ZPT];
#pragma unroll
    for (int z = 0; z < ZPT; z++) {
        const float fk = (float)(k0 + z);
        const float lx = fmaf(m02, fk, b0);
        const float ly = fmaf(m12, fk, b1);
        const float lz = fmaf(m22, fk, b2);

        const int valid =
            (int)(lx >= 0.0f) & (int)(lx <= (float)(HH - 1)) &
            (int)(ly >= 0.0f) & (int)(ly <= (float)(WW - 1)) &
            (int)(lz >= 0.0f) & (int)(lz <= (float)(DD - 1));

        const float fx = floorf(lx), fy = floorf(ly), fz = floorf(lz);
        const float tx = lx - fx, ty = ly - fy, tz = lz - fz;
        const int ix0 = (int)fx, iy0 = (int)fy, iz0 = (int)fz;

        // clamped base tap + clamped +1 offsets (0 when at/over either edge)
        const int xc = min(max(ix0, 0), HH - 1);
        const int yc = min(max(iy0, 0), WW - 1);
        const int zc = min(max(iz0, 0), DD - 1);
        const int ox = (ix0 >= 0 && ix0 < HH - 1) ? (WW * DD) : 0;
        const int oy = (iy0 >= 0 && iy0 < WW - 1) ? DD        : 0;
        const int oz = (iz0 >= 0 && iz0 < DD - 1) ? 1         : 0;

        const int base = (xc * WW + yc) * DD + zc;

        const float c000 = __ldg(vb + base);
        const float c001 = __ldg(vb + base + oz);
        const float c010 = __ldg(vb + base + oy);
        const float c011 = __ldg(vb + base + oy + oz);
        const float c100 = __ldg(vb + base + ox);
        const float c101 = __ldg(vb + base + ox + oz);
        const float c110 = __ldg(vb + base + ox + oy);
        const float c111 = __ldg(vb + base + ox + oy + oz);

        const float c00 = fmaf(tz, c001 - c000, c000);
        const float c01 = fmaf(tz, c011 - c010, c010);
        const float c10 = fmaf(tz, c101 - c100, c100);
        const float c11 = fmaf(tz, c111 - c110, c110);
        const float c0  = fmaf(ty, c01 - c00, c00);
        const float c1  = fmaf(ty, c11 - c10, c10);
        const float v   = fmaf(tx, c1 - c0, c0);

        res[z] = valid ? v : 0.0f;
    }

    __stcs(o4, make_float4(res[0], res[1], res[2], res[3]));
}

extern "C" void kernel_launch(void* const* d_in, const int* in_sizes, int n_in,
                              void* d_out, int out_size)
{
    const float* x    = (const float*)d_in[0];
    const float* mats = (const float*)d_in[1];
    float* out        = (float*)d_out;

    const int total_groups = BB * HH * WW * NG;      // 7,077,888
    const int threads = 256;
    const int blocks  = total_groups / threads;      // 27,648 exact
    affine_warp_kernel<<<blocks, threads>>>(x, mats, out);
}

// round 7
// speedup vs baseline: 1.5496x; 1.4566x over previous
#include <cuda_runtime.h>
#include <cuda_bf16.h>

// AffineAugment: per-batch rigid affine warp [B,H,W,D,1] fp32, trilinear, zero fill.
// B=4, H=W=D=192.
// Mapping: one thread = one output voxel; block = one z-row (192 threads),
// grid = (j, i, b). Warp spans only 32 consecutive z -> each tap LDG touches
// few cache lines (L1 wavefront-limited kernel), and no cross-z redundancy.
// Warp-coherent `valid` branch skips all tap loads in the zero-fill border.

#define BB  4
#define HH  192
#define WW  192
#define DD  192

__global__ void __launch_bounds__(192)
affine_warp_kernel(const float* __restrict__ x,
                   const float* __restrict__ mats,
                   float* __restrict__ out)
{
    const int k = threadIdx.x;
    const int j = blockIdx.x;
    const int i = blockIdx.y;
    const int b = blockIdx.z;

    const float* __restrict__ M = mats + b * 12;
    const float m00 = __ldg(M + 0), m01 = __ldg(M + 1), m02 = __ldg(M + 2), m03 = __ldg(M + 3);
    const float m10 = __ldg(M + 4), m11 = __ldg(M + 5), m12 = __ldg(M + 6), m13 = __ldg(M + 7);
    const float m20 = __ldg(M + 8), m21 = __ldg(M + 9), m22 = __ldg(M +10), m23 = __ldg(M +11);

    const float fi = (float)i, fj = (float)j, fk = (float)k;
    const float lx = fmaf(m00, fi, fmaf(m01, fj, fmaf(m02, fk, m03)));
    const float ly = fmaf(m10, fi, fmaf(m11, fj, fmaf(m12, fk, m13)));
    const float lz = fmaf(m20, fi, fmaf(m21, fj, fmaf(m22, fk, m23)));

    float v = 0.0f;
    const bool valid =
        (lx >= 0.0f) & (lx <= (float)(HH - 1)) &
        (ly >= 0.0f) & (ly <= (float)(WW - 1)) &
        (lz >= 0.0f) & (lz <= (float)(DD - 1));

    if (valid) {
        const int ix0 = __float2int_rd(lx);
        const int iy0 = __float2int_rd(ly);
        const int iz0 = __float2int_rd(lz);
        const float tx = lx - (float)ix0;
        const float ty = ly - (float)iy0;
        const float tz = lz - (float)iz0;

        // clamped +1 steps (0 at the top edge -> reads same voxel, weight handles it)
        const int ox = (ix0 < HH - 1) ? (WW * DD) : 0;
        const int oy = (iy0 < WW - 1) ? DD        : 0;
        const int oz = (iz0 < DD - 1) ? 1         : 0;

        const float* __restrict__ p0 =
            x + (size_t)b * (HH * WW * DD) + (ix0 * WW + iy0) * DD + iz0;
        const float* __restrict__ p1 = p0 + ox;      // +x row pair base
        const float* __restrict__ q0 = p0 + oy;      // +y row
        const float* __restrict__ q1 = p1 + oy;

        const float c000 = __ldg(p0);
        const float c001 = __ldg(p0 + oz);
        const float c010 = __ldg(q0);
        const float c011 = __ldg(q0 + oz);
        const float c100 = __ldg(p1);
        const float c101 = __ldg(p1 + oz);
        const float c110 = __ldg(q1);
        const float c111 = __ldg(q1 + oz);

        const float c00 = fmaf(tz, c001 - c000, c000);
        const float c01 = fmaf(tz, c011 - c010, c010);
        const float c10 = fmaf(tz, c101 - c100, c100);
        const float c11 = fmaf(tz, c111 - c110, c110);
        const float c0  = fmaf(ty, c01 - c00, c00);
        const float c1  = fmaf(ty, c11 - c10, c10);
        v = fmaf(tx, c1 - c0, c0);
    }

    __stcs(out + ((size_t)((b * HH + i) * WW + j) * DD + k), v);
}

extern "C" void kernel_launch(void* const* d_in, const int* in_sizes, int n_in,
                              void* d_out, int out_size)
{
    const float* x    = (const float*)d_in[0];
    const float* mats = (const float*)d_in[1];
    float* out        = (float*)d_out;

    dim3 grid(WW, HH, BB);     // (j, i, b)
    dim3 block(DD);            // k
    affine_warp_kernel<<<grid, block>>>(x, mats, out);
}